// round 1
// baseline (speedup 1.0000x reference)
#include <cuda_runtime.h>
#include <math.h>

#define NN 8192

// Scratch (allocation-free rule: device globals)
__device__ float g_deg [NN];
__device__ float g_dinv[NN];
__device__ float g_x1  [NN * 16];
__device__ float g_h2  [NN * 8];
__device__ float g_x2  [NN * 8];

// ---------------------------------------------------------------------------
// 1. zero scratch (deg + x1 + x2); x1 is largest at NN*16
__global__ void k_zero() {
    int i = blockIdx.x * blockDim.x + threadIdx.x;
    if (i < NN)      g_deg[i] = 0.0f;
    if (i < NN * 16) g_x1[i]  = 0.0f;
    if (i < NN * 8)  g_x2[i]  = 0.0f;
}

// 2. degree: deg[dst] += 1 per directed edge
__global__ void k_deg(const int* __restrict__ ei, int E) {
    int e = blockIdx.x * blockDim.x + threadIdx.x;
    if (e >= E) return;
    atomicAdd(&g_deg[ei[E + e]], 1.0f);
}

// 3. dinv = rsqrt(deg + 1)
__global__ void k_dinv() {
    int n = blockIdx.x * blockDim.x + threadIdx.x;
    if (n < NN) g_dinv[n] = rsqrtf(g_deg[n] + 1.0f);
}

// 4. conv1 scatter: x1[dst] += dinv[s]*dinv[d] * W1[src]  (16 feats)
__global__ void k_conv1(const int* __restrict__ ei,
                        const float* __restrict__ W1, int E) {
    int e = blockIdx.x * blockDim.x + threadIdx.x;
    if (e >= E) return;
    int s = ei[e];
    int d = ei[E + e];
    float nrm = g_dinv[s] * g_dinv[d];
    const float4* w = reinterpret_cast<const float4*>(W1 + (size_t)s * 16);
    float* xo = &g_x1[(size_t)d * 16];
#pragma unroll
    for (int q = 0; q < 4; q++) {
        float4 wv = w[q];
        atomicAdd(xo + 4 * q + 0, nrm * wv.x);
        atomicAdd(xo + 4 * q + 1, nrm * wv.y);
        atomicAdd(xo + 4 * q + 2, nrm * wv.z);
        atomicAdd(xo + 4 * q + 3, nrm * wv.w);
    }
}

// 5. per-node: x1 = relu(x1 + dinv^2*W1 + b1); h2 = x1 @ W2  (16x8)
__global__ void k_node1(const float* __restrict__ W1,
                        const float* __restrict__ b1,
                        const float* __restrict__ W2) {
    int n = blockIdx.x * blockDim.x + threadIdx.x;
    if (n >= NN) return;
    float sw = g_dinv[n] * g_dinv[n];
    float xf[16];
#pragma unroll
    for (int f = 0; f < 16; f++) {
        float v = g_x1[(size_t)n * 16 + f] + sw * W1[(size_t)n * 16 + f] + b1[f];
        xf[f] = fmaxf(v, 0.0f);
    }
#pragma unroll
    for (int j = 0; j < 8; j++) {
        float h = 0.0f;
#pragma unroll
        for (int f = 0; f < 16; f++) h += xf[f] * W2[f * 8 + j];
        g_h2[(size_t)n * 8 + j] = h;
    }
}

// 6. conv2 scatter: x2[dst] += norm * h2[src]  (8 feats)
__global__ void k_conv2(const int* __restrict__ ei, int E) {
    int e = blockIdx.x * blockDim.x + threadIdx.x;
    if (e >= E) return;
    int s = ei[e];
    int d = ei[E + e];
    float nrm = g_dinv[s] * g_dinv[d];
    const float4* h = reinterpret_cast<const float4*>(&g_h2[(size_t)s * 8]);
    float* xo = &g_x2[(size_t)d * 8];
#pragma unroll
    for (int q = 0; q < 2; q++) {
        float4 hv = h[q];
        atomicAdd(xo + 4 * q + 0, nrm * hv.x);
        atomicAdd(xo + 4 * q + 1, nrm * hv.y);
        atomicAdd(xo + 4 * q + 2, nrm * hv.z);
        atomicAdd(xo + 4 * q + 3, nrm * hv.w);
    }
}

// 7. per-node epilogue: x2 = relu(x2 + dinv^2*h2 + b2)
__global__ void k_node2(const float* __restrict__ b2) {
    int n = blockIdx.x * blockDim.x + threadIdx.x;
    if (n >= NN) return;
    float sw = g_dinv[n] * g_dinv[n];
#pragma unroll
    for (int f = 0; f < 8; f++) {
        float v = g_x2[(size_t)n * 8 + f] + sw * g_h2[(size_t)n * 8 + f] + b2[f];
        g_x2[(size_t)n * 8 + f] = fmaxf(v, 0.0f);
    }
}

// 8. bulk copy adjacency -> out (float4, the HBM-bound part)
__global__ void k_copy(const float4* __restrict__ src, float4* __restrict__ dst,
                       int n4) {
    int i = blockIdx.x * blockDim.x + threadIdx.x;
    if (i < n4) dst[i] = src[i];
}

// 9. orientation head: out[u,v] = sigmoid(ef @ Wfc + bfc); out[v,u] = 1 - it
__global__ void k_edgeout(const int* __restrict__ ue,
                          const float* __restrict__ Wfc,
                          const float* __restrict__ bfc,
                          float* __restrict__ out, int U) {
    int i = blockIdx.x * blockDim.x + threadIdx.x;
    if (i >= U) return;
    int u = ue[2 * i];
    int v = ue[2 * i + 1];
    float s = bfc[0];
#pragma unroll
    for (int f = 0; f < 8; f++) {
        s += g_x2[(size_t)u * 8 + f] * Wfc[f];
        s += g_x2[(size_t)v * 8 + f] * Wfc[8 + f];
    }
    float o = 1.0f / (1.0f + expf(-s));
    out[(size_t)u * NN + v] = o;
    out[(size_t)v * NN + u] = 1.0f - o;
}

extern "C" void kernel_launch(void* const* d_in, const int* in_sizes, int n_in,
                              void* d_out, int out_size) {
    const float* adj = (const float*)d_in[0];
    const float* W1  = (const float*)d_in[1];
    const float* b1  = (const float*)d_in[2];
    const float* W2  = (const float*)d_in[3];
    const float* b2  = (const float*)d_in[4];
    const float* Wfc = (const float*)d_in[5];
    const float* bfc = (const float*)d_in[6];
    const int*   ei  = (const int*)d_in[7];
    const int*   ue  = (const int*)d_in[8];

    int E = in_sizes[7] / 2;
    int U = in_sizes[8] / 2;

    const int B = 256;

    // scratch init (covers NN*16, the largest buffer)
    k_zero<<<(NN * 16 + B - 1) / B, B>>>();
    // degree + dinv
    k_deg <<<(E + B - 1) / B, B>>>(ei, E);
    k_dinv<<<(NN + B - 1) / B, B>>>();
    // layer 1
    k_conv1<<<(E + B - 1) / B, B>>>(ei, W1, E);
    k_node1<<<(NN + B - 1) / B, B>>>(W1, b1, W2);
    // layer 2
    k_conv2<<<(E + B - 1) / B, B>>>(ei, E);
    k_node2<<<(NN + B - 1) / B, B>>>(b2);
    // output: adjacency copy then orientation overwrite
    int n4 = out_size / 4;   // NN*NN is divisible by 4
    k_copy<<<(n4 + B - 1) / B, B>>>((const float4*)adj, (float4*)d_out, n4);
    k_edgeout<<<(U + B - 1) / B, B>>>(ue, Wfc, bfc, (float*)d_out, U);
}

// round 2
// speedup vs baseline: 1.1866x; 1.1866x over previous
#include <cuda_runtime.h>
#include <math.h>

#define NN 8192
#define EMAX 262144   // hard upper bound: 131072 undirected-dir + 131072 directed

// Scratch (allocation-free rule: device globals)
__device__ int   g_cnt   [NN];
__device__ int   g_fill  [NN];
__device__ int   g_rowptr[NN + 1];
__device__ int   g_col   [EMAX];
__device__ float g_dinv  [NN];
__device__ float g_h2    [NN * 8];
__device__ float g_x2    [NN * 8];

// ---------------------------------------------------------------------------
// 1. zero the two int counters
__global__ void k_zero() {
    int i = blockIdx.x * blockDim.x + threadIdx.x;
    if (i < NN) { g_cnt[i] = 0; g_fill[i] = 0; }
}

// 2. in-degree histogram over dst
__global__ void k_count(const int* __restrict__ ei, int E) {
    int e = blockIdx.x * blockDim.x + threadIdx.x;
    if (e < E) atomicAdd(&g_cnt[ei[E + e]], 1);
}

// 3. single-block exclusive scan of cnt -> rowptr, plus dinv = rsqrt(deg+1)
__global__ void k_scan() {
    __shared__ int sp[1024];
    int t = threadIdx.x;              // 1024 threads, 8 elems each
    int base = t * 8;
    int c[8], pre[8];
    int s = 0;
#pragma unroll
    for (int k = 0; k < 8; k++) {
        c[k] = g_cnt[base + k];
        pre[k] = s;
        s += c[k];
    }
    sp[t] = s;
    __syncthreads();
    // inclusive Hillis-Steele scan of 1024 partials
    for (int off = 1; off < 1024; off <<= 1) {
        int v = (t >= off) ? sp[t - off] : 0;
        __syncthreads();
        sp[t] += v;
        __syncthreads();
    }
    int off0 = sp[t] - s;             // exclusive offset for this thread
#pragma unroll
    for (int k = 0; k < 8; k++) {
        g_rowptr[base + k] = off0 + pre[k];
        g_dinv[base + k] = rsqrtf((float)c[k] + 1.0f);
    }
    if (t == 1023) g_rowptr[NN] = sp[1023];
}

// 4. CSR fill: bucket src by dst
__global__ void k_fill(const int* __restrict__ ei, int E) {
    int e = blockIdx.x * blockDim.x + threadIdx.x;
    if (e >= E) return;
    int s = ei[e];
    int d = ei[E + e];
    int p = g_rowptr[d] + atomicAdd(&g_fill[d], 1);
    g_col[p] = s;
}

// 5. conv1 gather + bias + ReLU + 16x8 matmul (16 lanes per node, shfl)
__global__ void k_conv1(const float* __restrict__ W1,
                        const float* __restrict__ b1,
                        const float* __restrict__ W2) {
    int tid  = blockIdx.x * blockDim.x + threadIdx.x;
    int n    = tid >> 4;              // 16 lanes per node
    int f    = tid & 15;
    if (n >= NN) return;
    int lane = threadIdx.x & 31;

    float dn  = g_dinv[n];
    int   beg = g_rowptr[n], end = g_rowptr[n + 1];
    float acc = 0.0f;
    for (int e = beg; e < end; e++) {
        int s = g_col[e];
        acc += g_dinv[s] * W1[(size_t)s * 16 + f];
    }
    float xf = fmaxf(dn * acc + dn * dn * W1[(size_t)n * 16 + f] + b1[f], 0.0f);

    // h2[n][j] = sum_k xf(k) * W2[k][j] for j = f < 8, via 16-lane shuffle group
    int gbase = lane & 16;            // 0 or 16: which half-warp group
    float h = 0.0f;
#pragma unroll
    for (int k = 0; k < 16; k++) {
        float xk = __shfl_sync(0xffffffffu, xf, gbase + k);
        h += xk * W2[k * 8 + (f & 7)];
    }
    if (f < 8) g_h2[(size_t)n * 8 + f] = h;
}

// 6. conv2 gather + bias + ReLU (8 lanes per node)
__global__ void k_conv2(const float* __restrict__ b2) {
    int tid = blockIdx.x * blockDim.x + threadIdx.x;
    int n   = tid >> 3;               // 8 lanes per node
    int j   = tid & 7;
    if (n >= NN) return;

    float dn  = g_dinv[n];
    int   beg = g_rowptr[n], end = g_rowptr[n + 1];
    float acc = 0.0f;
    for (int e = beg; e < end; e++) {
        int s = g_col[e];
        acc += g_dinv[s] * g_h2[(size_t)s * 8 + j];
    }
    float v = dn * acc + dn * dn * g_h2[(size_t)n * 8 + j] + b2[j];
    g_x2[(size_t)n * 8 + j] = fmaxf(v, 0.0f);
}

// 7. bulk copy adjacency -> out (float4, the HBM-bound part)
__global__ void k_copy(const float4* __restrict__ src, float4* __restrict__ dst,
                       int n4) {
    int i = blockIdx.x * blockDim.x + threadIdx.x;
    if (i < n4) dst[i] = src[i];
}

// 8. orientation head: out[u,v] = sigmoid(ef @ Wfc + bfc); out[v,u] = 1 - it
__global__ void k_edgeout(const int* __restrict__ ue,
                          const float* __restrict__ Wfc,
                          const float* __restrict__ bfc,
                          float* __restrict__ out, int U) {
    int i = blockIdx.x * blockDim.x + threadIdx.x;
    if (i >= U) return;
    int u = ue[2 * i];
    int v = ue[2 * i + 1];
    float s = bfc[0];
#pragma unroll
    for (int f = 0; f < 8; f++) {
        s += g_x2[(size_t)u * 8 + f] * Wfc[f];
        s += g_x2[(size_t)v * 8 + f] * Wfc[8 + f];
    }
    float o = 1.0f / (1.0f + expf(-s));
    out[(size_t)u * NN + v] = o;
    out[(size_t)v * NN + u] = 1.0f - o;
}

extern "C" void kernel_launch(void* const* d_in, const int* in_sizes, int n_in,
                              void* d_out, int out_size) {
    const float* adj = (const float*)d_in[0];
    const float* W1  = (const float*)d_in[1];
    const float* b1  = (const float*)d_in[2];
    const float* W2  = (const float*)d_in[3];
    const float* b2  = (const float*)d_in[4];
    const float* Wfc = (const float*)d_in[5];
    const float* bfc = (const float*)d_in[6];
    const int*   ei  = (const int*)d_in[7];
    const int*   ue  = (const int*)d_in[8];

    int E = in_sizes[7] / 2;
    int U = in_sizes[8] / 2;

    const int B = 256;

    // CSR build
    k_zero <<<(NN + B - 1) / B, B>>>();
    k_count<<<(E + B - 1) / B, B>>>(ei, E);
    k_scan <<<1, 1024>>>();
    k_fill <<<(E + B - 1) / B, B>>>(ei, E);
    // GCN layers (gather, no atomics)
    k_conv1<<<(NN * 16 + B - 1) / B, B>>>(W1, b1, W2);
    k_conv2<<<(NN * 8 + B - 1) / B, B>>>(b2);
    // output: adjacency copy then orientation overwrite
    int n4 = out_size / 4;            // NN*NN divisible by 4
    k_copy<<<(n4 + B - 1) / B, B>>>((const float4*)adj, (float4*)d_out, n4);
    k_edgeout<<<(U + B - 1) / B, B>>>(ue, Wfc, bfc, (float*)d_out, U);
}